// round 4
// baseline (speedup 1.0000x reference)
#include <cuda_runtime.h>
#include <cstdint>
#include <cstddef>

#define HID 256
#define LIN_DIM 652
#define OUTC 5

// Scratch: h0 (N*652) + h (N*256) + tmp (N*256) + agg (N*256) + z (N*256) + invdeg (N)
// N=50000 -> 50000*1677 = 83,850,000 floats
__device__ __align__(256) float g_scratch[84000000];

// ---------------------------------------------------------------------------
// Conv 3x3 VALID (8->8 ch, 11x11 -> 9x9) + flatten + concat bd_pred + relu
// 4 nodes per block, 72 threads per node (one per (c_out, out_row)).
// ---------------------------------------------------------------------------
__global__ __launch_bounds__(288)
void conv_kernel(const float* __restrict__ x, const float* __restrict__ w,
                 const float* __restrict__ cb, const float* __restrict__ bd,
                 float* __restrict__ h0, int N)
{
    __shared__ float sx[4][968];
    __shared__ float sw[576];
    __shared__ float sb[8];
    const int tid = threadIdx.x;
    const int node0 = blockIdx.x * 4;

    for (int i = tid; i < 576; i += 288) sw[i] = w[i];
    if (tid < 8) sb[tid] = cb[tid];
    for (int i = tid; i < 4 * 968; i += 288) {
        int ln = i / 968;
        int off = i - ln * 968;
        int n = node0 + ln;
        sx[ln][off] = (n < N) ? x[(size_t)n * 968 + off] : 0.f;
    }
    __syncthreads();

    const int ln = tid / 72;
    const int t  = tid - ln * 72;
    const int n  = node0 + ln;
    if (n >= N) return;
    const int co = t / 9;
    const int io = t - co * 9;

    float acc[9];
#pragma unroll
    for (int j = 0; j < 9; j++) acc[j] = sb[co];

#pragma unroll
    for (int ci = 0; ci < 8; ci++) {
#pragma unroll
        for (int di = 0; di < 3; di++) {
            const float* xr = &sx[ln][ci * 121 + (io + di) * 11];
            const int wbase = ((co * 8 + ci) * 3 + di) * 3;
            const float w0 = sw[wbase + 0];
            const float w1 = sw[wbase + 1];
            const float w2 = sw[wbase + 2];
            float xv[11];
#pragma unroll
            for (int q = 0; q < 11; q++) xv[q] = xr[q];
#pragma unroll
            for (int j = 0; j < 9; j++)
                acc[j] += xv[j] * w0 + xv[j + 1] * w1 + xv[j + 2] * w2;
        }
    }

    float* op = h0 + (size_t)n * LIN_DIM + co * 81 + io * 9;
#pragma unroll
    for (int j = 0; j < 9; j++) op[j] = fmaxf(acc[j], 0.f);

    if (t < 4)
        h0[(size_t)n * LIN_DIM + 648 + t] = fmaxf(bd[(size_t)n * 4 + t], 0.f);
}

// ---------------------------------------------------------------------------
// SGEMM: C[M,Nout] = A[M,K] @ W[Nout,K]^T (+ bias)
// 128x128 tile, BK=8, 256 threads, 8x8 per thread. Double-buffered fast path
// (requires full row/col tile; K tail handled with a masked load predicate).
// ---------------------------------------------------------------------------
__global__ __launch_bounds__(256, 2)
void sgemm_kernel(const float* __restrict__ A, const float* __restrict__ W,
                  const float* __restrict__ bias, float* __restrict__ C,
                  int M, int Nout, int K)
{
    __shared__ float As[2][8][132];
    __shared__ float Bs[2][8][132];
    const int row0 = blockIdx.y * 128;
    const int col0 = blockIdx.x * 128;
    const int tid = threadIdx.x;
    const int lk = tid & 7;
    const int lm = tid >> 3;   // 0..31
    const int tx = tid & 15;
    const int ty = tid >> 4;

    float acc[8][8];
#pragma unroll
    for (int i = 0; i < 8; i++)
#pragma unroll
        for (int j = 0; j < 8; j++) acc[i][j] = 0.f;

    const bool fast = (row0 + 128 <= M) && (col0 + 128 <= Nout);

    if (fast) {
        const float* Abase = A + (size_t)(row0 + lm) * K + lk;
        const float* Wbase = W + (size_t)(col0 + lm) * K + lk;
        float ra[4], rb[4];

        // prologue: load chunk 0
        {
#pragma unroll
            for (int p = 0; p < 4; p++) {
                ra[p] = Abase[(size_t)(p * 32) * K];
                rb[p] = Wbase[(size_t)(p * 32) * K];
            }
#pragma unroll
            for (int p = 0; p < 4; p++) {
                As[0][lk][lm + p * 32] = ra[p];
                Bs[0][lk][lm + p * 32] = rb[p];
            }
        }
        __syncthreads();

        int buf = 0;
        for (int k0 = 8; k0 < K; k0 += 8) {
            const bool ok = (k0 + lk < K);
#pragma unroll
            for (int p = 0; p < 4; p++) {
                ra[p] = ok ? Abase[(size_t)(p * 32) * K + k0] : 0.f;
                rb[p] = ok ? Wbase[(size_t)(p * 32) * K + k0] : 0.f;
            }
#pragma unroll
            for (int kk = 0; kk < 8; kk++) {
                const float4 a0 = *(const float4*)&As[buf][kk][ty * 8];
                const float4 a1 = *(const float4*)&As[buf][kk][ty * 8 + 4];
                const float4 b0 = *(const float4*)&Bs[buf][kk][tx * 8];
                const float4 b1 = *(const float4*)&Bs[buf][kk][tx * 8 + 4];
                const float a[8] = {a0.x, a0.y, a0.z, a0.w, a1.x, a1.y, a1.z, a1.w};
                const float b[8] = {b0.x, b0.y, b0.z, b0.w, b1.x, b1.y, b1.z, b1.w};
#pragma unroll
                for (int i = 0; i < 8; i++)
#pragma unroll
                    for (int j = 0; j < 8; j++) acc[i][j] += a[i] * b[j];
            }
#pragma unroll
            for (int p = 0; p < 4; p++) {
                As[buf ^ 1][lk][lm + p * 32] = ra[p];
                Bs[buf ^ 1][lk][lm + p * 32] = rb[p];
            }
            __syncthreads();
            buf ^= 1;
        }
        // final chunk
#pragma unroll
        for (int kk = 0; kk < 8; kk++) {
            const float4 a0 = *(const float4*)&As[buf][kk][ty * 8];
            const float4 a1 = *(const float4*)&As[buf][kk][ty * 8 + 4];
            const float4 b0 = *(const float4*)&Bs[buf][kk][tx * 8];
            const float4 b1 = *(const float4*)&Bs[buf][kk][tx * 8 + 4];
            const float a[8] = {a0.x, a0.y, a0.z, a0.w, a1.x, a1.y, a1.z, a1.w};
            const float b[8] = {b0.x, b0.y, b0.z, b0.w, b1.x, b1.y, b1.z, b1.w};
#pragma unroll
            for (int i = 0; i < 8; i++)
#pragma unroll
                for (int j = 0; j < 8; j++) acc[i][j] += a[i] * b[j];
        }
    } else {
        for (int k0 = 0; k0 < K; k0 += 8) {
            const int gk = k0 + lk;
#pragma unroll
            for (int p = 0; p < 4; p++) {
                const int m = lm + p * 32;
                float va = 0.f, vb = 0.f;
                if (gk < K) {
                    const int gr = row0 + m;
                    if (gr < M) va = A[(size_t)gr * K + gk];
                    const int gc = col0 + m;
                    if (gc < Nout) vb = W[(size_t)gc * K + gk];
                }
                As[0][lk][m] = va;
                Bs[0][lk][m] = vb;
            }
            __syncthreads();
#pragma unroll
            for (int kk = 0; kk < 8; kk++) {
                const float4 a0 = *(const float4*)&As[0][kk][ty * 8];
                const float4 a1 = *(const float4*)&As[0][kk][ty * 8 + 4];
                const float4 b0 = *(const float4*)&Bs[0][kk][tx * 8];
                const float4 b1 = *(const float4*)&Bs[0][kk][tx * 8 + 4];
                const float a[8] = {a0.x, a0.y, a0.z, a0.w, a1.x, a1.y, a1.z, a1.w};
                const float b[8] = {b0.x, b0.y, b0.z, b0.w, b1.x, b1.y, b1.z, b1.w};
#pragma unroll
                for (int i = 0; i < 8; i++)
#pragma unroll
                    for (int j = 0; j < 8; j++) acc[i][j] += a[i] * b[j];
            }
            __syncthreads();
        }
    }

#pragma unroll
    for (int i = 0; i < 8; i++) {
        const int r = row0 + ty * 8 + i;
        if (r >= M) continue;
#pragma unroll
        for (int j = 0; j < 8; j++) {
            const int c = col0 + tx * 8 + j;
            if (c >= Nout) continue;
            float v = acc[i][j];
            if (bias) v += bias[c];
            C[(size_t)r * Nout + c] = v;
        }
    }
}

// ---------------------------------------------------------------------------
// Fused SAGE layer GEMM:
//   C[M,256] = (invdeg[r] * agg[r]) @ Wl^T + bias_l + h @ Wr^T
// Treated as one K=512 GEMM: k<256 -> agg/Wl (A scaled at load), k>=256 -> h/Wr.
// ---------------------------------------------------------------------------
__global__ __launch_bounds__(256, 2)
void sage_gemm_kernel(const float* __restrict__ agg, const float* __restrict__ h,
                      const float* __restrict__ Wl, const float* __restrict__ Wr,
                      const float* __restrict__ bias, const float* __restrict__ invdeg,
                      float* __restrict__ C, int M)
{
    __shared__ float As[2][8][132];
    __shared__ float Bs[2][8][132];
    __shared__ float sdeg[128];
    const int row0 = blockIdx.y * 128;
    const int col0 = blockIdx.x * 128;   // always full: Nout=256
    const int tid = threadIdx.x;
    const int lk = tid & 7;
    const int lm = tid >> 3;
    const int tx = tid & 15;
    const int ty = tid >> 4;

    if (tid < 128)
        sdeg[tid] = (row0 + tid < M) ? invdeg[row0 + tid] : 0.f;

    float acc[8][8];
#pragma unroll
    for (int i = 0; i < 8; i++)
#pragma unroll
        for (int j = 0; j < 8; j++) acc[i][j] = 0.f;

    const bool fullM = (row0 + 128 <= M);
    float ra[4], rb[4];

    // chunk loader: kc in [0,64), seg 0 = agg/Wl (scaled), seg 1 = h/Wr
    auto load_chunk = [&](int kc) {
        const int seg = (kc >= 32);
        const int gk = ((kc & 31) << 3) + lk;
        const float* Ab = (seg ? h : agg);
        const float* Wb = (seg ? Wr : Wl);
#pragma unroll
        for (int p = 0; p < 4; p++) {
            const int m = lm + p * 32;
            const int gr = row0 + m;
            float va = 0.f;
            if (fullM || gr < M) va = Ab[(size_t)gr * HID + gk];
            if (!seg) va *= sdeg[m];
            ra[p] = va;
            rb[p] = Wb[(size_t)(col0 + m) * HID + gk];
        }
    };
    auto store_chunk = [&](int b) {
#pragma unroll
        for (int p = 0; p < 4; p++) {
            As[b][lk][lm + p * 32] = ra[p];
            Bs[b][lk][lm + p * 32] = rb[p];
        }
    };
    auto compute = [&](int b) {
#pragma unroll
        for (int kk = 0; kk < 8; kk++) {
            const float4 a0 = *(const float4*)&As[b][kk][ty * 8];
            const float4 a1 = *(const float4*)&As[b][kk][ty * 8 + 4];
            const float4 b0 = *(const float4*)&Bs[b][kk][tx * 8];
            const float4 b1 = *(const float4*)&Bs[b][kk][tx * 8 + 4];
            const float a[8] = {a0.x, a0.y, a0.z, a0.w, a1.x, a1.y, a1.z, a1.w};
            const float bb[8] = {b0.x, b0.y, b0.z, b0.w, b1.x, b1.y, b1.z, b1.w};
#pragma unroll
            for (int i = 0; i < 8; i++)
#pragma unroll
                for (int j = 0; j < 8; j++) acc[i][j] += a[i] * bb[j];
        }
    };

    __syncthreads();         // sdeg visible to all threads
    load_chunk(0);
    store_chunk(0);
    __syncthreads();
    int buf = 0;
    for (int kc = 1; kc < 64; kc++) {
        load_chunk(kc);
        compute(buf);
        store_chunk(buf ^ 1);
        __syncthreads();
        buf ^= 1;
    }
    compute(buf);

#pragma unroll
    for (int i = 0; i < 8; i++) {
        const int r = row0 + ty * 8 + i;
        if (r >= M) continue;
#pragma unroll
        for (int j = 0; j < 8; j++) {
            const int c = col0 + tx * 8 + j;
            C[(size_t)r * HID + c] = acc[i][j] + bias[c];
        }
    }
}

// ---------------------------------------------------------------------------
// Edge scatter-add: out[dst[e]] += feat[src[e]] over HID=256 floats.
// One warp per edge, vectorized red.global.add.v4.f32.
// edge_index arrives as int32 (harness downcasts int64 inputs).
// ---------------------------------------------------------------------------
__global__ void scatter_add_kernel(const float* __restrict__ feat,
                                   const int* __restrict__ ei,
                                   float* __restrict__ out, int E, int N)
{
    const int w = (blockIdx.x * blockDim.x + threadIdx.x) >> 5;
    const int lane = threadIdx.x & 31;
    if (w >= E) return;
    const int s = ei[w];
    const int d = ei[E + w];
    if ((unsigned)s >= (unsigned)N || (unsigned)d >= (unsigned)N) return;
    const float4* in = (const float4*)(feat + (size_t)s * HID);
    float* ob = out + (size_t)d * HID;
#pragma unroll
    for (int r = 0; r < 2; r++) {
        const float4 v = in[lane + 32 * r];
        float* p = ob + (size_t)(lane + 32 * r) * 4;
        asm volatile("red.global.add.v4.f32 [%0], {%1,%2,%3,%4};"
                     :: "l"(p), "f"(v.x), "f"(v.y), "f"(v.z), "f"(v.w)
                     : "memory");
    }
}

__global__ void deg_kernel(const int* __restrict__ ei, float* __restrict__ deg,
                           int E, int N)
{
    const int e = blockIdx.x * blockDim.x + threadIdx.x;
    if (e >= E) return;
    const int d = ei[E + e];
    if ((unsigned)d < (unsigned)N) atomicAdd(&deg[d], 1.0f);
}

__global__ void invert_kernel(float* __restrict__ d, int N)
{
    const int i = blockIdx.x * blockDim.x + threadIdx.x;
    if (i < N) d[i] = 1.f / fmaxf(d[i], 1.f);
}

// ---------------------------------------------------------------------------
// relu (+ optional layernorm over HID=256). One block (256 threads) per row.
// ---------------------------------------------------------------------------
__global__ void relu_ln_kernel(const float* __restrict__ in, float* __restrict__ out,
                               const float* __restrict__ gamma, const float* __restrict__ beta,
                               int doLN)
{
    const int r = blockIdx.x;
    const int t = threadIdx.x;
    const size_t idx = (size_t)r * HID + t;
    const float v = fmaxf(in[idx], 0.f);
    if (!doLN) { out[idx] = v; return; }

    float s = v, s2 = v * v;
#pragma unroll
    for (int off = 16; off; off >>= 1) {
        s  += __shfl_xor_sync(0xffffffffu, s, off);
        s2 += __shfl_xor_sync(0xffffffffu, s2, off);
    }
    __shared__ float sh[16];
    const int wid = t >> 5, lane = t & 31;
    if (lane == 0) { sh[wid] = s; sh[8 + wid] = s2; }
    __syncthreads();
    if (t == 0) {
        float S = 0.f, S2 = 0.f;
#pragma unroll
        for (int i = 0; i < 8; i++) { S += sh[i]; S2 += sh[8 + i]; }
        const float mu = S * (1.f / HID);
        const float var = S2 * (1.f / HID) - mu * mu;
        sh[0] = mu;
        sh[1] = rsqrtf(var + 1e-5f);
    }
    __syncthreads();
    const float mu = sh[0], rstd = sh[1];
    out[idx] = (v - mu) * rstd * gamma[t] + beta[t];
}

// ---------------------------------------------------------------------------
// Head: logits[5] = z @ mp2_w^T + b, then log_softmax. One warp per row.
// ---------------------------------------------------------------------------
__global__ void head_kernel(const float* __restrict__ z, const float* __restrict__ w2,
                            const float* __restrict__ b2, float* __restrict__ out, int N)
{
    const int row = blockIdx.x * 8 + (threadIdx.x >> 5);
    const int lane = threadIdx.x & 31;
    if (row >= N) return;
    const float* zr = z + (size_t)row * HID;
    float a0 = 0, a1 = 0, a2 = 0, a3 = 0, a4 = 0;
    for (int k = lane; k < HID; k += 32) {
        const float v = zr[k];
        a0 += v * w2[k];
        a1 += v * w2[256 + k];
        a2 += v * w2[512 + k];
        a3 += v * w2[768 + k];
        a4 += v * w2[1024 + k];
    }
#pragma unroll
    for (int off = 16; off; off >>= 1) {
        a0 += __shfl_xor_sync(0xffffffffu, a0, off);
        a1 += __shfl_xor_sync(0xffffffffu, a1, off);
        a2 += __shfl_xor_sync(0xffffffffu, a2, off);
        a3 += __shfl_xor_sync(0xffffffffu, a3, off);
        a4 += __shfl_xor_sync(0xffffffffu, a4, off);
    }
    if (lane == 0) {
        float l[5] = {a0 + b2[0], a1 + b2[1], a2 + b2[2], a3 + b2[3], a4 + b2[4]};
        float mx = l[0];
#pragma unroll
        for (int o = 1; o < 5; o++) mx = fmaxf(mx, l[o]);
        float se = 0.f;
#pragma unroll
        for (int o = 0; o < 5; o++) se += expf(l[o] - mx);
        const float lse = mx + logf(se);
#pragma unroll
        for (int o = 0; o < 5; o++) out[(size_t)row * 5 + o] = l[o] - lse;
    }
}

// ---------------------------------------------------------------------------
extern "C" void kernel_launch(void* const* d_in, const int* in_sizes, int n_in,
                              void* d_out, int out_size)
{
    const float* x          = (const float*)d_in[0];
    const float* bd         = (const float*)d_in[1];
    const int*   ei         = (const int*)d_in[2];   // int64 downcast to int32 by harness
    const float* conv_w     = (const float*)d_in[3];
    const float* conv_b     = (const float*)d_in[4];
    const float* lin_w      = (const float*)d_in[5];
    const float* lin_b      = (const float*)d_in[6];
    const float* lin_self_w = (const float*)d_in[7];
    const float* lin_self_b = (const float*)d_in[8];
    const float* sage_l_w   = (const float*)d_in[9];
    const float* sage_l_b   = (const float*)d_in[10];
    const float* sage_r_w   = (const float*)d_in[11];
    const float* ln_g       = (const float*)d_in[12];
    const float* ln_beta    = (const float*)d_in[13];
    const float* mp1_w      = (const float*)d_in[14];
    const float* mp1_b      = (const float*)d_in[15];
    const float* mp2_w      = (const float*)d_in[16];
    const float* mp2_b      = (const float*)d_in[17];

    const int N = in_sizes[1] / 4;   // bd_pred is [N,4]
    const int E = in_sizes[2] / 2;   // edge_index is [2,E]

    float* base = nullptr;
    cudaGetSymbolAddress((void**)&base, g_scratch);
    float* h0     = base;
    float* h      = h0  + (size_t)N * LIN_DIM;
    float* tmp    = h   + (size_t)N * HID;
    float* agg    = tmp + (size_t)N * HID;
    float* z      = agg + (size_t)N * HID;
    float* invdeg = z   + (size_t)N * HID;

    // Output layout derived from out_size (defensive — avoids OOB writes if
    // the harness packs outputs differently than assumed).
    float* emb_out;
    float* logp_out;
    float* extra = invdeg + N;   // spill target for whichever output isn't in d_out
    if (out_size >= N * (HID + OUTC)) {        // [emb | logp]
        emb_out  = (float*)d_out;
        logp_out = (float*)d_out + (size_t)N * HID;
    } else if (out_size == N * OUTC) {         // logp only
        emb_out  = extra;
        logp_out = (float*)d_out;
    } else {                                   // emb only
        emb_out  = (float*)d_out;
        logp_out = extra;
    }

    // 1. conv + flatten + concat + relu -> h0 [N, 652]
    conv_kernel<<<(N + 3) / 4, 288>>>(x, conv_w, conv_b, bd, h0, N);

    // 2. self_x -> h ; neigh -> tmp
    dim3 g2(2, (N + 127) / 128);
    sgemm_kernel<<<g2, 256>>>(h0, lin_self_w, lin_self_b, h,   N, HID, LIN_DIM);
    sgemm_kernel<<<g2, 256>>>(h0, lin_w,      lin_b,      tmp, N, HID, LIN_DIM);

    // 3. h += scatter_add(tmp[src] -> dst)
    scatter_add_kernel<<<(E + 7) / 8, 256>>>(tmp, ei, h, E, N);

    // 4. in-degree -> invdeg
    cudaMemsetAsync(invdeg, 0, (size_t)N * sizeof(float));
    deg_kernel<<<(E + 255) / 256, 256>>>(ei, invdeg, E, N);
    invert_kernel<<<(N + 255) / 256, 256>>>(invdeg, N);

    // 5. three SAGE layers (dual-GEMM fused per layer)
    for (int i = 0; i < 3; i++) {
        cudaMemsetAsync(agg, 0, (size_t)N * HID * sizeof(float));
        scatter_add_kernel<<<(E + 7) / 8, 256>>>(h, ei, agg, E, N);
        float* outb = (i == 2) ? emb_out : tmp;
        sage_gemm_kernel<<<g2, 256>>>(agg, h,
                                      sage_l_w + (size_t)i * HID * HID,
                                      sage_r_w + (size_t)i * HID * HID,
                                      sage_l_b + (size_t)i * HID,
                                      invdeg, outb, N);
        relu_ln_kernel<<<N, 256>>>(outb, h, ln_g + (size_t)i * HID,
                                   ln_beta + (size_t)i * HID, (i < 2) ? 1 : 0);
    }

    // 6. MLP head + log_softmax
    sgemm_kernel<<<g2, 256>>>(h, mp1_w, mp1_b, z, N, HID, HID);
    head_kernel<<<(N + 7) / 8, 256>>>(z, mp2_w, mp2_b, logp_out, N);
}

// round 5
// speedup vs baseline: 1.4974x; 1.4974x over previous
#include <cuda_runtime.h>
#include <cstdint>
#include <cstddef>

#define HID 256
#define LIN_DIM 652
#define OUTC 5

// Scratch: h0 (N*652) + h (N*256) + tmp (N*256) + agg (N*256) + z (N*256) + invdeg (N)
__device__ __align__(256) float g_scratch[84000000];

// ---------------------------------------------------------------------------
// Conv 3x3 VALID (8->8 ch, 11x11 -> 9x9) + flatten + concat bd_pred + relu
// ---------------------------------------------------------------------------
__global__ __launch_bounds__(288)
void conv_kernel(const float* __restrict__ x, const float* __restrict__ w,
                 const float* __restrict__ cb, const float* __restrict__ bd,
                 float* __restrict__ h0, int N)
{
    __shared__ float sx[4][968];
    __shared__ float sw[576];
    __shared__ float sb[8];
    const int tid = threadIdx.x;
    const int node0 = blockIdx.x * 4;

    for (int i = tid; i < 576; i += 288) sw[i] = w[i];
    if (tid < 8) sb[tid] = cb[tid];
    for (int i = tid; i < 4 * 968; i += 288) {
        int ln = i / 968;
        int off = i - ln * 968;
        int n = node0 + ln;
        sx[ln][off] = (n < N) ? x[(size_t)n * 968 + off] : 0.f;
    }
    __syncthreads();

    const int ln = tid / 72;
    const int t  = tid - ln * 72;
    const int n  = node0 + ln;
    if (n >= N) return;
    const int co = t / 9;
    const int io = t - co * 9;

    float acc[9];
#pragma unroll
    for (int j = 0; j < 9; j++) acc[j] = sb[co];

#pragma unroll
    for (int ci = 0; ci < 8; ci++) {
#pragma unroll
        for (int di = 0; di < 3; di++) {
            const float* xr = &sx[ln][ci * 121 + (io + di) * 11];
            const int wbase = ((co * 8 + ci) * 3 + di) * 3;
            const float w0 = sw[wbase + 0];
            const float w1 = sw[wbase + 1];
            const float w2 = sw[wbase + 2];
            float xv[11];
#pragma unroll
            for (int q = 0; q < 11; q++) xv[q] = xr[q];
#pragma unroll
            for (int j = 0; j < 9; j++)
                acc[j] += xv[j] * w0 + xv[j + 1] * w1 + xv[j + 2] * w2;
        }
    }

    float* op = h0 + (size_t)n * LIN_DIM + co * 81 + io * 9;
#pragma unroll
    for (int j = 0; j < 9; j++) op[j] = fmaxf(acc[j], 0.f);

    if (t < 4)
        h0[(size_t)n * LIN_DIM + 648 + t] = fmaxf(bd[(size_t)n * 4 + t], 0.f);
}

// ---------------------------------------------------------------------------
// Tensor-core GEMM with 2-term bf16 split (hi+lo), fp32 accumulate.
//   C[M,Nout] = (rowScale ? diag(rowScale) : I) * A0 @ W0^T  [K0 cols]
//             + A1 @ W1^T                                    [K1 cols, optional]
//             + bias
// A*, W* are fp32 row-major with K-stride = their segment's K.
// Block 128x128, BK=16, 8 warps (warp tile 32x64), mma.m16n8k16.bf16.
// Per product: acc += Ahi*Bhi + Ahi*Blo + Alo*Bhi  (lo*lo dropped, ~2^-34)
// ---------------------------------------------------------------------------
#define BM 128
#define BN 128
#define SSTR 136   // smem row stride (u32 elems) for conflict reduction

__device__ __forceinline__ void f32_to_bf16x2_pair(uint32_t& hi, uint32_t& lo,
                                                   float f0, float f1)
{
    uint32_t h;
    asm("cvt.rn.bf16x2.f32 %0, %1, %2;" : "=r"(h) : "f"(f1), "f"(f0));
    const float h0 = __uint_as_float(h << 16);
    const float h1 = __uint_as_float(h & 0xffff0000u);
    const float s0 = f0 - h0;
    const float s1 = f1 - h1;
    asm("cvt.rn.bf16x2.f32 %0, %1, %2;" : "=r"(lo) : "f"(s1), "f"(s0));
    hi = h;
}

__device__ __forceinline__ void mma_bf16(float* c, const uint32_t* a, const uint32_t* b)
{
    asm volatile(
        "mma.sync.aligned.m16n8k16.row.col.f32.bf16.bf16.f32 "
        "{%0,%1,%2,%3}, {%4,%5,%6,%7}, {%8,%9}, {%0,%1,%2,%3};"
        : "+f"(c[0]), "+f"(c[1]), "+f"(c[2]), "+f"(c[3])
        : "r"(a[0]), "r"(a[1]), "r"(a[2]), "r"(a[3]), "r"(b[0]), "r"(b[1]));
}

__global__ __launch_bounds__(256)
void mma_gemm(const float* __restrict__ A0, const float* __restrict__ W0, int K0,
              const float* __restrict__ A1, const float* __restrict__ W1, int K1,
              const float* __restrict__ rowScale, const float* __restrict__ bias,
              float* __restrict__ C, int M, int Nout)
{
    __shared__ uint32_t AsH[2][8][SSTR];
    __shared__ uint32_t AsL[2][8][SSTR];
    __shared__ uint32_t BsH[2][8][SSTR];
    __shared__ uint32_t BsL[2][8][SSTR];
    __shared__ float sdeg[BM];

    const int tid  = threadIdx.x;
    const int row0 = blockIdx.y * BM;
    const int col0 = blockIdx.x * BN;
    const int wid  = tid >> 5;
    const int lane = tid & 31;
    const int wm   = (wid & 3) * 32;   // warp m-offset in tile
    const int wn   = (wid >> 2) * 64;  // warp n-offset in tile
    const int g    = lane >> 2;        // 0..7
    const int tg   = lane & 3;         // 0..3

    if (tid < BM)
        sdeg[tid] = (rowScale && row0 + tid < M) ? rowScale[row0 + tid] : 1.f;

    float acc[2][8][4];
#pragma unroll
    for (int t = 0; t < 2; t++)
#pragma unroll
        for (int u = 0; u < 8; u++)
#pragma unroll
            for (int q = 0; q < 4; q++) acc[t][u][q] = 0.f;

    const int nc0 = (K0 + 15) >> 4;
    const int nc1 = (K1 + 15) >> 4;
    const int nch = nc0 + nc1;

    float2 ra[4], rb[4];

    // stage-load chunk c into registers (global -> regs)
    auto load_global = [&](int c) {
        const bool seg1 = (c >= nc0);
        const float* A = seg1 ? A1 : A0;
        const float* W = seg1 ? W1 : W0;
        const int K  = seg1 ? K1 : K0;
        const int k0 = (seg1 ? (c - nc0) : c) << 4;
        const bool doScale = (rowScale != nullptr) && !seg1;
#pragma unroll
        for (int i = 0; i < 4; i++) {
            const int p  = tid + i * 256;       // 0..1023
            const int r  = p >> 3;              // row/col within tile
            const int k2 = p & 7;               // k-pair index
            const int k  = k0 + (k2 << 1);
            float2 va = make_float2(0.f, 0.f);
            const int grow = row0 + r;
            if (grow < M && k < K)
                va = *(const float2*)&A[(size_t)grow * K + k];
            if (doScale) {
                const float s = sdeg[r];
                va.x *= s; va.y *= s;
            }
            ra[i] = va;
            float2 vb = make_float2(0.f, 0.f);
            if (k < K)
                vb = *(const float2*)&W[(size_t)(col0 + r) * K + k];
            rb[i] = vb;
        }
    };

    // convert staged regs -> bf16 hi/lo smem buffer
    auto convert_store = [&](int b) {
#pragma unroll
        for (int i = 0; i < 4; i++) {
            const int p  = tid + i * 256;
            const int r  = p >> 3;
            const int k2 = p & 7;
            uint32_t hi, lo;
            f32_to_bf16x2_pair(hi, lo, ra[i].x, ra[i].y);
            AsH[b][k2][r] = hi;
            AsL[b][k2][r] = lo;
            f32_to_bf16x2_pair(hi, lo, rb[i].x, rb[i].y);
            BsH[b][k2][r] = hi;
            BsL[b][k2][r] = lo;
        }
    };

    auto compute = [&](int b) {
        uint32_t ah[2][4], al[2][4], bh[8][2], bl[8][2];
#pragma unroll
        for (int t = 0; t < 2; t++) {
            const int base = wm + t * 16 + g;
            ah[t][0] = AsH[b][tg][base];
            ah[t][1] = AsH[b][tg][base + 8];
            ah[t][2] = AsH[b][tg + 4][base];
            ah[t][3] = AsH[b][tg + 4][base + 8];
            al[t][0] = AsL[b][tg][base];
            al[t][1] = AsL[b][tg][base + 8];
            al[t][2] = AsL[b][tg + 4][base];
            al[t][3] = AsL[b][tg + 4][base + 8];
        }
#pragma unroll
        for (int u = 0; u < 8; u++) {
            const int bn = wn + u * 8 + g;
            bh[u][0] = BsH[b][tg][bn];
            bh[u][1] = BsH[b][tg + 4][bn];
            bl[u][0] = BsL[b][tg][bn];
            bl[u][1] = BsL[b][tg + 4][bn];
        }
#pragma unroll
        for (int t = 0; t < 2; t++)
#pragma unroll
            for (int u = 0; u < 8; u++) {
                mma_bf16(acc[t][u], ah[t], bh[u]);
                mma_bf16(acc[t][u], ah[t], bl[u]);
                mma_bf16(acc[t][u], al[t], bh[u]);
            }
    };

    __syncthreads();            // sdeg visible
    load_global(0);
    convert_store(0);
    __syncthreads();

    int buf = 0;
    for (int c = 1; c < nch; c++) {
        load_global(c);
        compute(buf);
        convert_store(buf ^ 1);
        __syncthreads();
        buf ^= 1;
    }
    compute(buf);

    // epilogue
#pragma unroll
    for (int t = 0; t < 2; t++) {
        const int r_ = row0 + wm + t * 16 + g;
#pragma unroll
        for (int u = 0; u < 8; u++) {
            const int c_ = col0 + wn + u * 8 + 2 * tg;
            float b0 = 0.f, b1 = 0.f;
            if (bias) { b0 = bias[c_]; b1 = bias[c_ + 1]; }
            if (r_ < M) {
                float2 v = make_float2(acc[t][u][0] + b0, acc[t][u][1] + b1);
                *(float2*)&C[(size_t)r_ * Nout + c_] = v;
            }
            if (r_ + 8 < M) {
                float2 v = make_float2(acc[t][u][2] + b0, acc[t][u][3] + b1);
                *(float2*)&C[(size_t)(r_ + 8) * Nout + c_] = v;
            }
        }
    }
}

// ---------------------------------------------------------------------------
// Edge scatter-add: out[dst[e]] += feat[src[e]] over HID=256 floats.
// ---------------------------------------------------------------------------
__global__ void scatter_add_kernel(const float* __restrict__ feat,
                                   const int* __restrict__ ei,
                                   float* __restrict__ out, int E, int N)
{
    const int w = (blockIdx.x * blockDim.x + threadIdx.x) >> 5;
    const int lane = threadIdx.x & 31;
    if (w >= E) return;
    const int s = ei[w];
    const int d = ei[E + w];
    if ((unsigned)s >= (unsigned)N || (unsigned)d >= (unsigned)N) return;
    const float4* in = (const float4*)(feat + (size_t)s * HID);
    float* ob = out + (size_t)d * HID;
#pragma unroll
    for (int r = 0; r < 2; r++) {
        const float4 v = in[lane + 32 * r];
        float* p = ob + (size_t)(lane + 32 * r) * 4;
        asm volatile("red.global.add.v4.f32 [%0], {%1,%2,%3,%4};"
                     :: "l"(p), "f"(v.x), "f"(v.y), "f"(v.z), "f"(v.w)
                     : "memory");
    }
}

__global__ void deg_kernel(const int* __restrict__ ei, float* __restrict__ deg,
                           int E, int N)
{
    const int e = blockIdx.x * blockDim.x + threadIdx.x;
    if (e >= E) return;
    const int d = ei[E + e];
    if ((unsigned)d < (unsigned)N) atomicAdd(&deg[d], 1.0f);
}

__global__ void invert_kernel(float* __restrict__ d, int N)
{
    const int i = blockIdx.x * blockDim.x + threadIdx.x;
    if (i < N) d[i] = 1.f / fmaxf(d[i], 1.f);
}

// ---------------------------------------------------------------------------
// relu (+ optional layernorm over HID=256). One block (256 threads) per row.
// ---------------------------------------------------------------------------
__global__ void relu_ln_kernel(const float* __restrict__ in, float* __restrict__ out,
                               const float* __restrict__ gamma, const float* __restrict__ beta,
                               int doLN)
{
    const int r = blockIdx.x;
    const int t = threadIdx.x;
    const size_t idx = (size_t)r * HID + t;
    const float v = fmaxf(in[idx], 0.f);
    if (!doLN) { out[idx] = v; return; }

    float s = v, s2 = v * v;
#pragma unroll
    for (int off = 16; off; off >>= 1) {
        s  += __shfl_xor_sync(0xffffffffu, s, off);
        s2 += __shfl_xor_sync(0xffffffffu, s2, off);
    }
    __shared__ float sh[16];
    const int wid = t >> 5, lane = t & 31;
    if (lane == 0) { sh[wid] = s; sh[8 + wid] = s2; }
    __syncthreads();
    if (t == 0) {
        float S = 0.f, S2 = 0.f;
#pragma unroll
        for (int i = 0; i < 8; i++) { S += sh[i]; S2 += sh[8 + i]; }
        const float mu = S * (1.f / HID);
        const float var = S2 * (1.f / HID) - mu * mu;
        sh[0] = mu;
        sh[1] = rsqrtf(var + 1e-5f);
    }
    __syncthreads();
    const float mu = sh[0], rstd = sh[1];
    out[idx] = (v - mu) * rstd * gamma[t] + beta[t];
}

// ---------------------------------------------------------------------------
// Head: logits[5] = z @ mp2_w^T + b, then log_softmax. One warp per row.
// ---------------------------------------------------------------------------
__global__ void head_kernel(const float* __restrict__ z, const float* __restrict__ w2,
                            const float* __restrict__ b2, float* __restrict__ out, int N)
{
    const int row = blockIdx.x * 8 + (threadIdx.x >> 5);
    const int lane = threadIdx.x & 31;
    if (row >= N) return;
    const float* zr = z + (size_t)row * HID;
    float a0 = 0, a1 = 0, a2 = 0, a3 = 0, a4 = 0;
    for (int k = lane; k < HID; k += 32) {
        const float v = zr[k];
        a0 += v * w2[k];
        a1 += v * w2[256 + k];
        a2 += v * w2[512 + k];
        a3 += v * w2[768 + k];
        a4 += v * w2[1024 + k];
    }
#pragma unroll
    for (int off = 16; off; off >>= 1) {
        a0 += __shfl_xor_sync(0xffffffffu, a0, off);
        a1 += __shfl_xor_sync(0xffffffffu, a1, off);
        a2 += __shfl_xor_sync(0xffffffffu, a2, off);
        a3 += __shfl_xor_sync(0xffffffffu, a3, off);
        a4 += __shfl_xor_sync(0xffffffffu, a4, off);
    }
    if (lane == 0) {
        float l[5] = {a0 + b2[0], a1 + b2[1], a2 + b2[2], a3 + b2[3], a4 + b2[4]};
        float mx = l[0];
#pragma unroll
        for (int o = 1; o < 5; o++) mx = fmaxf(mx, l[o]);
        float se = 0.f;
#pragma unroll
        for (int o = 0; o < 5; o++) se += expf(l[o] - mx);
        const float lse = mx + logf(se);
#pragma unroll
        for (int o = 0; o < 5; o++) out[(size_t)row * 5 + o] = l[o] - lse;
    }
}

// ---------------------------------------------------------------------------
extern "C" void kernel_launch(void* const* d_in, const int* in_sizes, int n_in,
                              void* d_out, int out_size)
{
    const float* x          = (const float*)d_in[0];
    const float* bd         = (const float*)d_in[1];
    const int*   ei         = (const int*)d_in[2];   // int64 downcast to int32 by harness
    const float* conv_w     = (const float*)d_in[3];
    const float* conv_b     = (const float*)d_in[4];
    const float* lin_w      = (const float*)d_in[5];
    const float* lin_b      = (const float*)d_in[6];
    const float* lin_self_w = (const float*)d_in[7];
    const float* lin_self_b = (const float*)d_in[8];
    const float* sage_l_w   = (const float*)d_in[9];
    const float* sage_l_b   = (const float*)d_in[10];
    const float* sage_r_w   = (const float*)d_in[11];
    const float* ln_g       = (const float*)d_in[12];
    const float* ln_beta    = (const float*)d_in[13];
    const float* mp1_w      = (const float*)d_in[14];
    const float* mp1_b      = (const float*)d_in[15];
    const float* mp2_w      = (const float*)d_in[16];
    const float* mp2_b      = (const float*)d_in[17];

    const int N = in_sizes[1] / 4;   // bd_pred is [N,4]
    const int E = in_sizes[2] / 2;   // edge_index is [2,E]

    float* base = nullptr;
    cudaGetSymbolAddress((void**)&base, g_scratch);
    float* h0     = base;
    float* h      = h0  + (size_t)N * LIN_DIM;
    float* tmp    = h   + (size_t)N * HID;
    float* agg    = tmp + (size_t)N * HID;
    float* z      = agg + (size_t)N * HID;
    float* invdeg = z   + (size_t)N * HID;

    // Output layout derived from out_size.
    float* emb_out;
    float* logp_out;
    float* extra = invdeg + N;
    if (out_size >= N * (HID + OUTC)) {
        emb_out  = (float*)d_out;
        logp_out = (float*)d_out + (size_t)N * HID;
    } else if (out_size == N * OUTC) {
        emb_out  = extra;
        logp_out = (float*)d_out;
    } else {
        emb_out  = (float*)d_out;
        logp_out = extra;
    }

    // 1. conv + flatten + concat + relu -> h0 [N, 652]
    conv_kernel<<<(N + 3) / 4, 288>>>(x, conv_w, conv_b, bd, h0, N);

    // 2. self_x -> h ; neigh -> tmp    (tensor-core GEMMs, K=652)
    dim3 g2(2, (N + 127) / 128);
    mma_gemm<<<g2, 256>>>(h0, lin_self_w, LIN_DIM, nullptr, nullptr, 0,
                          nullptr, lin_self_b, h, N, HID);
    mma_gemm<<<g2, 256>>>(h0, lin_w, LIN_DIM, nullptr, nullptr, 0,
                          nullptr, lin_b, tmp, N, HID);

    // 3. h += scatter_add(tmp[src] -> dst)
    scatter_add_kernel<<<(E + 7) / 8, 256>>>(tmp, ei, h, E, N);

    // 4. in-degree -> invdeg
    cudaMemsetAsync(invdeg, 0, (size_t)N * sizeof(float));
    deg_kernel<<<(E + 255) / 256, 256>>>(ei, invdeg, E, N);
    invert_kernel<<<(N + 255) / 256, 256>>>(invdeg, N);

    // 5. three SAGE layers: fused dual GEMM (K=256+256) on tensor cores
    for (int i = 0; i < 3; i++) {
        cudaMemsetAsync(agg, 0, (size_t)N * HID * sizeof(float));
        scatter_add_kernel<<<(E + 7) / 8, 256>>>(h, ei, agg, E, N);
        float* outb = (i == 2) ? emb_out : tmp;
        mma_gemm<<<g2, 256>>>(agg, sage_l_w + (size_t)i * HID * HID, HID,
                              h,   sage_r_w + (size_t)i * HID * HID, HID,
                              invdeg, sage_l_b + (size_t)i * HID, outb, N, HID);
        relu_ln_kernel<<<N, 256>>>(outb, h, ln_g + (size_t)i * HID,
                                   ln_beta + (size_t)i * HID, (i < 2) ? 1 : 0);
    }

    // 6. MLP head + log_softmax
    mma_gemm<<<g2, 256>>>(h, mp1_w, HID, nullptr, nullptr, 0,
                          nullptr, mp1_b, z, N, HID);
    head_kernel<<<(N + 7) / 8, 256>>>(z, mp2_w, mp2_b, logp_out, N);
}

// round 9
// speedup vs baseline: 1.8148x; 1.2119x over previous
#include <cuda_runtime.h>
#include <cstdint>
#include <cstddef>

#define HID 256
#define LIN_DIM 652
#define OUTC 5

// Scratch floats: h0 (N*652) + h + tmp + agg + z (each N*256) + spill (N)
// plus int region for CSR: cnt(N) rowptr(N+1) cursor(N) col(E) part(P)
__device__ __align__(256) float g_scratch[85000000];

// ---------------------------------------------------------------------------
// Conv 3x3 VALID (8->8 ch, 11x11 -> 9x9) + flatten + concat bd_pred + relu
// ---------------------------------------------------------------------------
__global__ __launch_bounds__(288)
void conv_kernel(const float* __restrict__ x, const float* __restrict__ w,
                 const float* __restrict__ cb, const float* __restrict__ bd,
                 float* __restrict__ h0, int N)
{
    __shared__ float sx[4][968];
    __shared__ float sw[576];
    __shared__ float sb[8];
    const int tid = threadIdx.x;
    const int node0 = blockIdx.x * 4;

    for (int i = tid; i < 576; i += 288) sw[i] = w[i];
    if (tid < 8) sb[tid] = cb[tid];
    for (int i = tid; i < 4 * 968; i += 288) {
        int ln = i / 968;
        int off = i - ln * 968;
        int n = node0 + ln;
        sx[ln][off] = (n < N) ? x[(size_t)n * 968 + off] : 0.f;
    }
    __syncthreads();

    const int ln = tid / 72;
    const int t  = tid - ln * 72;
    const int n  = node0 + ln;
    if (n >= N) return;
    const int co = t / 9;
    const int io = t - co * 9;

    float acc[9];
#pragma unroll
    for (int j = 0; j < 9; j++) acc[j] = sb[co];

#pragma unroll
    for (int ci = 0; ci < 8; ci++) {
#pragma unroll
        for (int di = 0; di < 3; di++) {
            const float* xr = &sx[ln][ci * 121 + (io + di) * 11];
            const int wbase = ((co * 8 + ci) * 3 + di) * 3;
            const float w0 = sw[wbase + 0];
            const float w1 = sw[wbase + 1];
            const float w2 = sw[wbase + 2];
            float xv[11];
#pragma unroll
            for (int q = 0; q < 11; q++) xv[q] = xr[q];
#pragma unroll
            for (int j = 0; j < 9; j++)
                acc[j] += xv[j] * w0 + xv[j + 1] * w1 + xv[j + 2] * w2;
        }
    }

    float* op = h0 + (size_t)n * LIN_DIM + co * 81 + io * 9;
#pragma unroll
    for (int j = 0; j < 9; j++) op[j] = fmaxf(acc[j], 0.f);

    if (t < 4)
        h0[(size_t)n * LIN_DIM + 648 + t] = fmaxf(bd[(size_t)n * 4 + t], 0.f);
}

// ---------------------------------------------------------------------------
// Tensor-core GEMM with 2-term bf16 split (hi+lo), fp32 accumulate.
//   C[M,Nout] = A0 @ W0^T [K0] + A1 @ W1^T [K1, optional] + bias
// Block 128x128, BK=16, 8 warps (warp tile 32x64), mma.m16n8k16.bf16.
// acc += Ahi*Bhi + Ahi*Blo + Alo*Bhi  (lo*lo dropped, ~2^-34)
// ---------------------------------------------------------------------------
#define BM 128
#define BN 128
#define SSTR 136

__device__ __forceinline__ void f32_to_bf16x2_pair(uint32_t& hi, uint32_t& lo,
                                                   float f0, float f1)
{
    uint32_t h;
    asm("cvt.rn.bf16x2.f32 %0, %1, %2;" : "=r"(h) : "f"(f1), "f"(f0));
    const float h0 = __uint_as_float(h << 16);
    const float h1 = __uint_as_float(h & 0xffff0000u);
    const float s0 = f0 - h0;
    const float s1 = f1 - h1;
    asm("cvt.rn.bf16x2.f32 %0, %1, %2;" : "=r"(lo) : "f"(s1), "f"(s0));
    hi = h;
}

__device__ __forceinline__ void mma_bf16(float* c, const uint32_t* a, const uint32_t* b)
{
    asm volatile(
        "mma.sync.aligned.m16n8k16.row.col.f32.bf16.bf16.f32 "
        "{%0,%1,%2,%3}, {%4,%5,%6,%7}, {%8,%9}, {%0,%1,%2,%3};"
        : "+f"(c[0]), "+f"(c[1]), "+f"(c[2]), "+f"(c[3])
        : "r"(a[0]), "r"(a[1]), "r"(a[2]), "r"(a[3]), "r"(b[0]), "r"(b[1]));
}

__global__ __launch_bounds__(256)
void mma_gemm(const float* __restrict__ A0, const float* __restrict__ W0, int K0,
              const float* __restrict__ A1, const float* __restrict__ W1, int K1,
              const float* __restrict__ bias,
              float* __restrict__ C, int M, int Nout)
{
    __shared__ uint32_t AsH[2][8][SSTR];
    __shared__ uint32_t AsL[2][8][SSTR];
    __shared__ uint32_t BsH[2][8][SSTR];
    __shared__ uint32_t BsL[2][8][SSTR];

    const int tid  = threadIdx.x;
    const int row0 = blockIdx.y * BM;
    const int col0 = blockIdx.x * BN;
    const int wid  = tid >> 5;
    const int lane = tid & 31;
    const int wm   = (wid & 3) * 32;
    const int wn   = (wid >> 2) * 64;
    const int g    = lane >> 2;
    const int tg   = lane & 3;

    float acc[2][8][4];
#pragma unroll
    for (int t = 0; t < 2; t++)
#pragma unroll
        for (int u = 0; u < 8; u++)
#pragma unroll
            for (int q = 0; q < 4; q++) acc[t][u][q] = 0.f;

    const int nc0 = (K0 + 15) >> 4;
    const int nc1 = (K1 + 15) >> 4;
    const int nch = nc0 + nc1;

    float2 ra[4], rb[4];

    auto load_global = [&](int c) {
        const bool seg1 = (c >= nc0);
        const float* A = seg1 ? A1 : A0;
        const float* W = seg1 ? W1 : W0;
        const int K  = seg1 ? K1 : K0;
        const int k0 = (seg1 ? (c - nc0) : c) << 4;
#pragma unroll
        for (int i = 0; i < 4; i++) {
            const int p  = tid + i * 256;
            const int r  = p >> 3;
            const int k2 = p & 7;
            const int k  = k0 + (k2 << 1);
            float2 va = make_float2(0.f, 0.f);
            const int grow = row0 + r;
            if (grow < M && k < K)
                va = *(const float2*)&A[(size_t)grow * K + k];
            ra[i] = va;
            float2 vb = make_float2(0.f, 0.f);
            if (k < K)
                vb = *(const float2*)&W[(size_t)(col0 + r) * K + k];
            rb[i] = vb;
        }
    };

    auto convert_store = [&](int b) {
#pragma unroll
        for (int i = 0; i < 4; i++) {
            const int p  = tid + i * 256;
            const int r  = p >> 3;
            const int k2 = p & 7;
            uint32_t hi, lo;
            f32_to_bf16x2_pair(hi, lo, ra[i].x, ra[i].y);
            AsH[b][k2][r] = hi;
            AsL[b][k2][r] = lo;
            f32_to_bf16x2_pair(hi, lo, rb[i].x, rb[i].y);
            BsH[b][k2][r] = hi;
            BsL[b][k2][r] = lo;
        }
    };

    auto compute = [&](int b) {
        uint32_t ah[2][4], al[2][4], bh[8][2], bl[8][2];
#pragma unroll
        for (int t = 0; t < 2; t++) {
            const int base = wm + t * 16 + g;
            ah[t][0] = AsH[b][tg][base];
            ah[t][1] = AsH[b][tg][base + 8];
            ah[t][2] = AsH[b][tg + 4][base];
            ah[t][3] = AsH[b][tg + 4][base + 8];
            al[t][0] = AsL[b][tg][base];
            al[t][1] = AsL[b][tg][base + 8];
            al[t][2] = AsL[b][tg + 4][base];
            al[t][3] = AsL[b][tg + 4][base + 8];
        }
#pragma unroll
        for (int u = 0; u < 8; u++) {
            const int bn = wn + u * 8 + g;
            bh[u][0] = BsH[b][tg][bn];
            bh[u][1] = BsH[b][tg + 4][bn];
            bl[u][0] = BsL[b][tg][bn];
            bl[u][1] = BsL[b][tg + 4][bn];
        }
#pragma unroll
        for (int t = 0; t < 2; t++)
#pragma unroll
            for (int u = 0; u < 8; u++) {
                mma_bf16(acc[t][u], ah[t], bh[u]);
                mma_bf16(acc[t][u], ah[t], bl[u]);
                mma_bf16(acc[t][u], al[t], bh[u]);
            }
    };

    load_global(0);
    convert_store(0);
    __syncthreads();

    int buf = 0;
    for (int c = 1; c < nch; c++) {
        load_global(c);
        compute(buf);
        convert_store(buf ^ 1);
        __syncthreads();
        buf ^= 1;
    }
    compute(buf);

#pragma unroll
    for (int t = 0; t < 2; t++) {
        const int r_ = row0 + wm + t * 16 + g;
#pragma unroll
        for (int u = 0; u < 8; u++) {
            const int c_ = col0 + wn + u * 8 + 2 * tg;
            float b0 = 0.f, b1 = 0.f;
            if (bias) { b0 = bias[c_]; b1 = bias[c_ + 1]; }
            if (r_ < M) {
                float2 v = make_float2(acc[t][u][0] + b0, acc[t][u][1] + b1);
                *(float2*)&C[(size_t)r_ * Nout + c_] = v;
            }
            if (r_ + 8 < M) {
                float2 v = make_float2(acc[t][u][2] + b0, acc[t][u][3] + b1);
                *(float2*)&C[(size_t)(r_ + 8) * Nout + c_] = v;
            }
        }
    }
}

// ---------------------------------------------------------------------------
// CSR build: histogram -> 3-phase exclusive scan -> cursor fill
// ---------------------------------------------------------------------------
__global__ void hist_kernel(const int* __restrict__ ei, int* __restrict__ cnt,
                            int E, int N)
{
    const int e = blockIdx.x * blockDim.x + threadIdx.x;
    if (e >= E) return;
    const int d = ei[E + e];
    if ((unsigned)d < (unsigned)N) atomicAdd(&cnt[d], 1);
}

__global__ void scan_pass1(const int* __restrict__ cnt, int* __restrict__ part, int N)
{
    __shared__ int sh[256];
    const int b = blockIdx.x, t = threadIdx.x;
    const int base = b * 1024;
    int s = 0;
#pragma unroll
    for (int i = 0; i < 4; i++) {
        const int idx = base + t * 4 + i;
        if (idx < N) s += cnt[idx];
    }
    sh[t] = s;
    __syncthreads();
    for (int off = 128; off; off >>= 1) {
        if (t < off) sh[t] += sh[t + off];
        __syncthreads();
    }
    if (t == 0) part[b] = sh[0];
}

// parallel exclusive scan over partials (P <= 64 fast path; serial fallback)
__global__ void scan_pass2(int* __restrict__ part, int P,
                           int* __restrict__ rowptr, int N, int E)
{
    const int t = threadIdx.x;
    if (P <= 64) {
        __shared__ int sh[64];
        int v = (t < P) ? part[t] : 0;
        sh[t] = v;
        __syncthreads();
        for (int off = 1; off < 64; off <<= 1) {
            const int x = (t >= off) ? sh[t - off] : 0;
            __syncthreads();
            sh[t] += x;
            __syncthreads();
        }
        if (t < P) part[t] = sh[t] - v;   // exclusive
        if (t == 0) rowptr[N] = E;
    } else if (t == 0) {
        int run = 0;
        for (int i = 0; i < P; i++) { const int v = part[i]; part[i] = run; run += v; }
        rowptr[N] = E;
    }
}

__global__ void scan_pass3(const int* __restrict__ cnt, const int* __restrict__ part,
                           int* __restrict__ rowptr, int N)
{
    __shared__ int sh[256];
    const int b = blockIdx.x, t = threadIdx.x;
    const int base = b * 1024;
    int v[4];
    int s = 0;
#pragma unroll
    for (int i = 0; i < 4; i++) {
        const int idx = base + t * 4 + i;
        v[i] = (idx < N) ? cnt[idx] : 0;
        s += v[i];
    }
    sh[t] = s;
    __syncthreads();
    for (int off = 1; off < 256; off <<= 1) {
        const int x = (t >= off) ? sh[t - off] : 0;
        __syncthreads();
        sh[t] += x;
        __syncthreads();
    }
    int excl = (t ? sh[t - 1] : 0) + part[b];
#pragma unroll
    for (int i = 0; i < 4; i++) {
        const int idx = base + t * 4 + i;
        if (idx < N) { rowptr[idx] = excl; excl += v[i]; }
    }
}

__global__ void fill_col(const int* __restrict__ ei, const int* __restrict__ rowptr,
                         int* __restrict__ cursor, int* __restrict__ col, int E, int N)
{
    const int e = blockIdx.x * blockDim.x + threadIdx.x;
    if (e >= E) return;
    const int s = ei[e];
    const int d = ei[E + e];
    if ((unsigned)s >= (unsigned)N || (unsigned)d >= (unsigned)N) return;
    const int pos = rowptr[d] + atomicAdd(&cursor[d], 1);
    col[pos] = s;
}

// ---------------------------------------------------------------------------
// CSR gather aggregation (float4-vectorized).
// 4 rows per block; 64 threads per row, each owning one float4 column slice.
//   mode 0: out[r] += sum_{nbr} feat[nbr]
//   mode 1: out[r]  = mean_{nbr} feat[nbr]   (deg>=1 clamp)
// ---------------------------------------------------------------------------
__global__ __launch_bounds__(256)
void gather_kernel(const float* __restrict__ feat,
                   const int* __restrict__ rowptr,
                   const int* __restrict__ col,
                   float* __restrict__ out, int mode, int N)
{
    const int r = blockIdx.x * 4 + (threadIdx.x >> 6);
    const int t = threadIdx.x & 63;          // float4 lane: 64 * 16B = 1024B row
    if (r >= N) return;
    const int beg = rowptr[r], end = rowptr[r + 1];

    float4 s = make_float4(0.f, 0.f, 0.f, 0.f);
    int e = beg;
    for (; e + 1 < end; e += 2) {
        const int s0 = col[e], s1 = col[e + 1];
        const float4 v0 = ((const float4*)(feat + (size_t)s0 * HID))[t];
        const float4 v1 = ((const float4*)(feat + (size_t)s1 * HID))[t];
        s.x += v0.x + v1.x;
        s.y += v0.y + v1.y;
        s.z += v0.z + v1.z;
        s.w += v0.w + v1.w;
    }
    if (e < end) {
        const float4 v = ((const float4*)(feat + (size_t)col[e] * HID))[t];
        s.x += v.x; s.y += v.y; s.z += v.z; s.w += v.w;
    }

    float4* op = (float4*)(out + (size_t)r * HID) + t;
    if (mode) {
        const int d = end - beg;
        const float inv = 1.f / (float)(d > 0 ? d : 1);
        *op = make_float4(s.x * inv, s.y * inv, s.z * inv, s.w * inv);
    } else {
        const float4 o = *op;
        *op = make_float4(o.x + s.x, o.y + s.y, o.z + s.z, o.w + s.w);
    }
}

// ---------------------------------------------------------------------------
// relu (+ optional layernorm over HID=256). One block (256 threads) per row.
// ---------------------------------------------------------------------------
__global__ void relu_ln_kernel(const float* __restrict__ in, float* __restrict__ out,
                               const float* __restrict__ gamma, const float* __restrict__ beta,
                               int doLN)
{
    const int r = blockIdx.x;
    const int t = threadIdx.x;
    const size_t idx = (size_t)r * HID + t;
    const float v = fmaxf(in[idx], 0.f);
    if (!doLN) { out[idx] = v; return; }

    float s = v, s2 = v * v;
#pragma unroll
    for (int off = 16; off; off >>= 1) {
        s  += __shfl_xor_sync(0xffffffffu, s, off);
        s2 += __shfl_xor_sync(0xffffffffu, s2, off);
    }
    __shared__ float sh[16];
    const int wid = t >> 5, lane = t & 31;
    if (lane == 0) { sh[wid] = s; sh[8 + wid] = s2; }
    __syncthreads();
    if (t == 0) {
        float S = 0.f, S2 = 0.f;
#pragma unroll
        for (int i = 0; i < 8; i++) { S += sh[i]; S2 += sh[8 + i]; }
        const float mu = S * (1.f / HID);
        const float var = S2 * (1.f / HID) - mu * mu;
        sh[0] = mu;
        sh[1] = rsqrtf(var + 1e-5f);
    }
    __syncthreads();
    const float mu = sh[0], rstd = sh[1];
    out[idx] = (v - mu) * rstd * gamma[t] + beta[t];
}

// ---------------------------------------------------------------------------
// Head: logits[5] = z @ mp2_w^T + b, then log_softmax. One warp per row.
// ---------------------------------------------------------------------------
__global__ void head_kernel(const float* __restrict__ z, const float* __restrict__ w2,
                            const float* __restrict__ b2, float* __restrict__ out, int N)
{
    const int row = blockIdx.x * 8 + (threadIdx.x >> 5);
    const int lane = threadIdx.x & 31;
    if (row >= N) return;
    const float* zr = z + (size_t)row * HID;
    float a0 = 0, a1 = 0, a2 = 0, a3 = 0, a4 = 0;
    for (int k = lane; k < HID; k += 32) {
        const float v = zr[k];
        a0 += v * w2[k];
        a1 += v * w2[256 + k];
        a2 += v * w2[512 + k];
        a3 += v * w2[768 + k];
        a4 += v * w2[1024 + k];
    }
#pragma unroll
    for (int off = 16; off; off >>= 1) {
        a0 += __shfl_xor_sync(0xffffffffu, a0, off);
        a1 += __shfl_xor_sync(0xffffffffu, a1, off);
        a2 += __shfl_xor_sync(0xffffffffu, a2, off);
        a3 += __shfl_xor_sync(0xffffffffu, a3, off);
        a4 += __shfl_xor_sync(0xffffffffu, a4, off);
    }
    if (lane == 0) {
        float l[5] = {a0 + b2[0], a1 + b2[1], a2 + b2[2], a3 + b2[3], a4 + b2[4]};
        float mx = l[0];
#pragma unroll
        for (int o = 1; o < 5; o++) mx = fmaxf(mx, l[o]);
        float se = 0.f;
#pragma unroll
        for (int o = 0; o < 5; o++) se += expf(l[o] - mx);
        const float lse = mx + logf(se);
#pragma unroll
        for (int o = 0; o < 5; o++) out[(size_t)row * 5 + o] = l[o] - lse;
    }
}

// ---------------------------------------------------------------------------
extern "C" void kernel_launch(void* const* d_in, const int* in_sizes, int n_in,
                              void* d_out, int out_size)
{
    const float* x          = (const float*)d_in[0];
    const float* bd         = (const float*)d_in[1];
    const int*   ei         = (const int*)d_in[2];   // int64 downcast to int32 by harness
    const float* conv_w     = (const float*)d_in[3];
    const float* conv_b     = (const float*)d_in[4];
    const float* lin_w      = (const float*)d_in[5];
    const float* lin_b      = (const float*)d_in[6];
    const float* lin_self_w = (const float*)d_in[7];
    const float* lin_self_b = (const float*)d_in[8];
    const float* sage_l_w   = (const float*)d_in[9];
    const float* sage_l_b   = (const float*)d_in[10];
    const float* sage_r_w   = (const float*)d_in[11];
    const float* ln_g       = (const float*)d_in[12];
    const float* ln_beta    = (const float*)d_in[13];
    const float* mp1_w      = (const float*)d_in[14];
    const float* mp1_b      = (const float*)d_in[15];
    const float* mp2_w      = (const float*)d_in[16];
    const float* mp2_b      = (const float*)d_in[17];

    const int N = in_sizes[1] / 4;   // bd_pred is [N,4]
    const int E = in_sizes[2] / 2;   // edge_index is [2,E]

    float* base = nullptr;
    cudaGetSymbolAddress((void**)&base, g_scratch);
    float* h0     = base;
    float* h      = h0  + (size_t)N * LIN_DIM;
    float* tmp    = h   + (size_t)N * HID;
    float* agg    = tmp + (size_t)N * HID;
    float* z      = agg + (size_t)N * HID;
    float* fend   = z   + (size_t)N * HID;

    // int region for CSR
    int* ibase  = (int*)(fend + N);      // leave N floats spare (logp spill)
    int* cnt    = ibase;
    int* rowptr = cnt + N;
    int* cursor = rowptr + N + 1;
    int* colarr = cursor + N;
    int* part   = colarr + E;
    const int P = (N + 1023) / 1024;

    // Output layout derived from out_size.
    float* emb_out;
    float* logp_out;
    float* extra = fend;                 // spill target
    if (out_size >= N * (HID + OUTC)) {
        emb_out  = (float*)d_out;
        logp_out = (float*)d_out + (size_t)N * HID;
    } else if (out_size == N * OUTC) {
        emb_out  = extra;
        logp_out = (float*)d_out;
    } else {
        emb_out  = (float*)d_out;
        logp_out = extra;
    }

    // 1. conv + flatten + concat + relu -> h0 [N, 652]
    conv_kernel<<<(N + 3) / 4, 288>>>(x, conv_w, conv_b, bd, h0, N);

    // 2. self_x -> h ; neigh -> tmp    (tensor-core GEMMs, K=652)
    dim3 g2(2, (N + 127) / 128);
    mma_gemm<<<g2, 256>>>(h0, lin_self_w, LIN_DIM, nullptr, nullptr, 0,
                          lin_self_b, h, N, HID);
    mma_gemm<<<g2, 256>>>(h0, lin_w, LIN_DIM, nullptr, nullptr, 0,
                          lin_b, tmp, N, HID);

    // 3. CSR build (dst-indexed)
    cudaMemsetAsync(cnt, 0, (size_t)N * sizeof(int));
    cudaMemsetAsync(cursor, 0, (size_t)N * sizeof(int));
    hist_kernel<<<(E + 255) / 256, 256>>>(ei, cnt, E, N);
    scan_pass1<<<P, 256>>>(cnt, part, N);
    scan_pass2<<<1, 64>>>(part, P, rowptr, N, E);
    scan_pass3<<<P, 256>>>(cnt, part, rowptr, N);
    fill_col<<<(E + 255) / 256, 256>>>(ei, rowptr, cursor, colarr, E, N);

    // 4. h += gather_sum(tmp)
    gather_kernel<<<(N + 3) / 4, 256>>>(tmp, rowptr, colarr, h, 0, N);

    // 5. three SAGE layers: gather-mean then fused dual GEMM (K=256+256)
    for (int i = 0; i < 3; i++) {
        gather_kernel<<<(N + 3) / 4, 256>>>(h, rowptr, colarr, agg, 1, N);
        float* outb = (i == 2) ? emb_out : tmp;
        mma_gemm<<<g2, 256>>>(agg, sage_l_w + (size_t)i * HID * HID, HID,
                              h,   sage_r_w + (size_t)i * HID * HID, HID,
                              sage_l_b + (size_t)i * HID, outb, N, HID);
        relu_ln_kernel<<<N, 256>>>(outb, h, ln_g + (size_t)i * HID,
                                   ln_beta + (size_t)i * HID, (i < 2) ? 1 : 0);
    }

    // 6. MLP head + log_softmax
    mma_gemm<<<g2, 256>>>(h, mp1_w, HID, nullptr, nullptr, 0,
                          mp1_b, z, N, HID);
    head_kernel<<<(N + 7) / 8, 256>>>(z, mp2_w, mp2_b, logp_out, N);
}